// round 13
// baseline (speedup 1.0000x reference)
#include <cuda_runtime.h>
#include <cuda_fp16.h>
#include <cstdint>
#include <math.h>

// ---------------------------------------------------------------------------
// PcLinearBlock: ARCH=(1024,2048,2048,512), BATCH=4096, STEPS=20, LR=0.1
// fp16 mma.sync m16n8k16 + ldmatrix.x4 fragment loads, fp32 accumulate.
// 128x128x64 tile, cp.async 3-stage single-sync pipeline, full XOR swizzle
// (16B chunk ^= row&7) -> conflict-free ldmatrix. Plain row-major fp16
// operand shadows; exact fp32 state carries epilogues/reductions/output.
// Error/update phases fused into single launches via blockIdx routing.
// ---------------------------------------------------------------------------

#define MB 4096
#define D0 1024
#define D1 2048
#define D2 2048
#define D3 512
#define NSTEPS 20
#define LRC 0.1f

// ---- exact fp32 state ----
__device__ __align__(128) float g_r1[(size_t)MB * D1];
__device__ __align__(128) float g_r2[(size_t)MB * D2];
__device__ __align__(128) float g_r3[(size_t)MB * D3];
__device__ __align__(128) float g_e0[(size_t)MB * D0];
__device__ __align__(128) float g_e1[(size_t)MB * D1];
__device__ __align__(128) float g_e2[(size_t)MB * D2];
// ---- fp16-rounded row-major GEMM operand shadows ----
__device__ __align__(128) __half g_xr [(size_t)MB * D0];
__device__ __align__(128) __half g_r1r[(size_t)MB * D1];
__device__ __align__(128) __half g_r2r[(size_t)MB * D2];
__device__ __align__(128) __half g_r3r[(size_t)MB * D3];
__device__ __align__(128) __half g_e0r[(size_t)MB * D0];
__device__ __align__(128) __half g_e1r[(size_t)MB * D1];
__device__ __align__(128) __half g_e2r[(size_t)MB * D2];
__device__ __align__(128) __half g_W0r[(size_t)D1 * D0];
__device__ __align__(128) __half g_W1r[(size_t)D2 * D1];
__device__ __align__(128) __half g_W2r[(size_t)D3 * D2];
__device__ __align__(128) __half g_Wt0[(size_t)D0 * D1];
__device__ __align__(128) __half g_Wt1[(size_t)D1 * D2];
__device__ __align__(128) __half g_Wt2[(size_t)D2 * D3];
__device__ float g_part[4096];

// ---------------------------------------------------------------------------
// helpers
// ---------------------------------------------------------------------------
__device__ __forceinline__ uint32_t s2u(const void* p) {
    uint32_t a;
    asm("{ .reg .u64 t; cvta.to.shared.u64 t, %1; cvt.u32.u64 %0, t; }"
        : "=r"(a) : "l"(p));
    return a;
}
__device__ __forceinline__ void cp16(uint32_t dst, const void* src) {
    asm volatile("cp.async.cg.shared.global [%0], [%1], 16;"
                 :: "r"(dst), "l"(src));
}
__device__ __forceinline__ void ldm4(uint32_t* r, uint32_t addr) {
    asm volatile(
        "ldmatrix.sync.aligned.m8n8.x4.shared.b16 {%0,%1,%2,%3}, [%4];"
        : "=r"(r[0]), "=r"(r[1]), "=r"(r[2]), "=r"(r[3]) : "r"(addr));
}
__device__ __forceinline__ void mma16(float* c, const uint32_t* a,
                                      uint32_t b0, uint32_t b1) {
    asm volatile(
        "mma.sync.aligned.m16n8k16.row.col.f32.f16.f16.f32 "
        "{%0,%1,%2,%3}, {%4,%5,%6,%7}, {%8,%9}, {%0,%1,%2,%3};"
        : "+f"(c[0]), "+f"(c[1]), "+f"(c[2]), "+f"(c[3])
        : "r"(a[0]), "r"(a[1]), "r"(a[2]), "r"(a[3]), "r"(b0), "r"(b1));
}
__device__ __forceinline__ float fast_tanh(float x) {
    float e = __expf(2.0f * x);
    return 1.0f - 2.0f / (e + 1.0f);
}

// ---------------------------------------------------------------------------
// GEMM body:  C[m,n] = sum_k A[m,k]*B[n,k]   (fp16 row-major operands)
// 128x128x64 tile, 256 thr, 3-stage cp.async, ONE __syncthreads per chunk.
// ldmatrix.x4 fragment loads; swizzle: 16B chunk ^= (row & 7).
// EPI 0: D = tanh(acc + X[n]);  EPI 1: D = X - tanh(acc);
// EPI 2: D += LR*(acc - X).   Writes exact fp32 D and fp16 shadow Dr.
// ---------------------------------------------------------------------------
#define STG_B   32768            // A 16KB + B 16KB (128 rows x 128B each)
#define SMEM_SZ (3 * STG_B)

template <int EPI>
__device__ __forceinline__ void gemm_body(
    const __half* __restrict__ A, const __half* __restrict__ B,
    const float* __restrict__ X, float* __restrict__ D,
    __half* __restrict__ Dr, int N, int K, int bm, int bn, char* smem)
{
    const uint32_t sb = s2u(smem);
    const int tid = threadIdx.x;
    const int wid = tid >> 5, lane = tid & 31;
    const int gid = lane >> 2, tig = lane & 3;
    const int warp_m = wid & 1;
    const int warp_n = wid >> 1;

    // global->smem: thread t copies 64B of row t/2 (16B chunks, swizzled)
    const int ar = tid >> 1;
    const int half = tid & 1;
    const __half* gA = A + (size_t)(bm + ar) * K + half * 32;
    const __half* gB = B + (size_t)(bn + ar) * K + half * 32;
    uint32_t sw[4];
#pragma unroll
    for (int i = 0; i < 4; i++) {
        int cc = half * 4 + i;
        sw[i] = (uint32_t)(ar * 128 + ((cc ^ (ar & 7)) * 16));
    }

    const int KT = K >> 6;            // 64 fp16 per chunk = 128B row

    // ---- prologue: stages 0,1
#pragma unroll
    for (int kt = 0; kt < 2; kt++) {
        uint32_t base = sb + kt * STG_B;
        const __half* pa = gA + kt * 64;
        const __half* pb = gB + kt * 64;
#pragma unroll
        for (int i = 0; i < 4; i++) cp16(base + sw[i], pa + i * 8);
#pragma unroll
        for (int i = 0; i < 4; i++) cp16(base + 16384 + sw[i], pb + i * 8);
        asm volatile("cp.async.commit_group;" ::: "memory");
    }

    float acc[4][4][4];
#pragma unroll
    for (int mi = 0; mi < 4; mi++)
#pragma unroll
        for (int ni = 0; ni < 4; ni++)
#pragma unroll
            for (int r = 0; r < 4; r++) acc[mi][ni][r] = 0.f;

    // ldmatrix per-lane addressing:
    //   lanes 0-7:  rows 0-7,  k-lo | lanes 8-15: rows 8-15, k-lo
    //   lanes 16-23: rows 0-7, k-hi | lanes 24-31: rows 8-15, k-hi
    const int mrow = lane & 15;       // row within 16-row fragment
    const int khi  = lane >> 4;       // 0 = k0-7 chunk, 1 = k8-15 chunk
    const int rx   = mrow & 7;        // swizzle key (row & 7)
    const uint32_t arow0 = (uint32_t)((warp_m * 64 + mrow) * 128);
    const uint32_t brow0 = (uint32_t)((warp_n * 32 + mrow) * 128);

    // ---- mainloop: one barrier per 64-k chunk
    for (int kt = 0; kt < KT; kt++) {
        asm volatile("cp.async.wait_group 1;" ::: "memory");
        __syncthreads();
        const int kn = kt + 2;
        if (kn < KT) {
            uint32_t base = sb + (kn % 3) * STG_B;
            const __half* pa = gA + kn * 64;
            const __half* pb = gB + kn * 64;
#pragma unroll
            for (int i = 0; i < 4; i++) cp16(base + sw[i], pa + i * 8);
#pragma unroll
            for (int i = 0; i < 4; i++) cp16(base + 16384 + sw[i], pb + i * 8);
        }
        asm volatile("cp.async.commit_group;" ::: "memory");

        const uint32_t sA = sb + (kt % 3) * STG_B;
        const uint32_t sB = sA + 16384;

#pragma unroll
        for (int ks = 0; ks < 4; ks++) {            // 4 x k16 per chunk
            const uint32_t cb = (uint32_t)(((ks * 2 + khi) ^ rx) * 16);
            uint32_t a[4][4], b[2][4];
#pragma unroll
            for (int mi = 0; mi < 4; mi++)
                ldm4(a[mi], sA + arow0 + (uint32_t)(mi * 16 * 128) + cb);
#pragma unroll
            for (int nj = 0; nj < 2; nj++)
                ldm4(b[nj], sB + brow0 + (uint32_t)(nj * 16 * 128) + cb);
#pragma unroll
            for (int mi = 0; mi < 4; mi++)
#pragma unroll
                for (int ni = 0; ni < 4; ni++)
                    mma16(acc[mi][ni], a[mi],
                          b[ni >> 1][ni & 1], b[ni >> 1][(ni & 1) + 2]);
        }
    }

    // ---- fused epilogue: exact fp32 store + fp16 shadow
#pragma unroll
    for (int mi = 0; mi < 4; mi++) {
        const int gm = bm + warp_m * 64 + mi * 16 + gid;
#pragma unroll
        for (int ni = 0; ni < 4; ni++) {
            const int gn = bn + warp_n * 32 + ni * 8 + 2 * tig;   // even
            const size_t i0 = (size_t)gm * N + gn;
            const size_t i1 = i0 + (size_t)8 * N;
            const float* c = acc[mi][ni];
            float2 o0, o1;
            if (EPI == 0) {
                float b0v = X[gn], b1v = X[gn + 1];
                o0.x = fast_tanh(c[0] + b0v);
                o0.y = fast_tanh(c[1] + b1v);
                o1.x = fast_tanh(c[2] + b0v);
                o1.y = fast_tanh(c[3] + b1v);
            } else if (EPI == 1) {
                float2 x0 = *reinterpret_cast<const float2*>(&X[i0]);
                float2 x1 = *reinterpret_cast<const float2*>(&X[i1]);
                o0.x = x0.x - fast_tanh(c[0]);
                o0.y = x0.y - fast_tanh(c[1]);
                o1.x = x1.x - fast_tanh(c[2]);
                o1.y = x1.y - fast_tanh(c[3]);
            } else {
                float2 x0 = *reinterpret_cast<const float2*>(&X[i0]);
                float2 x1 = *reinterpret_cast<const float2*>(&X[i1]);
                float2 d0 = *reinterpret_cast<const float2*>(&D[i0]);
                float2 d1 = *reinterpret_cast<const float2*>(&D[i1]);
                o0.x = d0.x + LRC * (c[0] - x0.x);
                o0.y = d0.y + LRC * (c[1] - x0.y);
                o1.x = d1.x + LRC * (c[2] - x1.x);
                o1.y = d1.y + LRC * (c[3] - x1.y);
            }
            *reinterpret_cast<float2*>(&D[i0]) = o0;
            *reinterpret_cast<float2*>(&D[i1]) = o1;
            *reinterpret_cast<__half2*>(&Dr[i0]) =
                __halves2half2(__float2half_rn(o0.x), __float2half_rn(o0.y));
            *reinterpret_cast<__half2*>(&Dr[i1]) =
                __halves2half2(__float2half_rn(o1.x), __float2half_rn(o1.y));
        }
    }
}

// ---- single-GEMM kernel (feedforward) ----
template <int EPI>
__global__ void __launch_bounds__(256, 2)
tc_gemm(const __half* __restrict__ A, const __half* __restrict__ B,
        const float* __restrict__ X, float* __restrict__ D,
        __half* __restrict__ Dr, int N, int K)
{
    extern __shared__ char smem[];
    gemm_body<EPI>(A, B, X, D, Dr, N, K,
                   blockIdx.y * 128, blockIdx.x * 128, smem);
}

// ---- fused 3-GEMM kernel (error / update phases) ----
struct Sub {
    const __half* A; const __half* B; const float* X;
    float* D; __half* Dr; int N; int K;
};

template <int EPI>
__global__ void __launch_bounds__(256, 2)
tc_gemm3(Sub s0, Sub s1, Sub s2, int t0, int t1)
{
    extern __shared__ char smem[];
    const int bx = blockIdx.x;
    const __half *A, *B; const float* X; float* D; __half* Dr; int N, K, bn;
    if (bx < t0)      { A=s0.A; B=s0.B; X=s0.X; D=s0.D; Dr=s0.Dr;
                        N=s0.N; K=s0.K; bn = bx * 128; }
    else if (bx < t1) { A=s1.A; B=s1.B; X=s1.X; D=s1.D; Dr=s1.Dr;
                        N=s1.N; K=s1.K; bn = (bx - t0) * 128; }
    else              { A=s2.A; B=s2.B; X=s2.X; D=s2.D; Dr=s2.Dr;
                        N=s2.N; K=s2.K; bn = (bx - t1) * 128; }
    gemm_body<EPI>(A, B, X, D, Dr, N, K, blockIdx.y * 128, bn, smem);
}

// ---------------------------------------------------------------------------
// prep kernels: fp32 -> fp16 (and transpose for Wt); plain row-major
// ---------------------------------------------------------------------------
__global__ void round_h(const float* __restrict__ src,
                        __half* __restrict__ dst, long long n)
{
    long long i = (long long)blockIdx.x * blockDim.x + threadIdx.x;
    if (i * 2 < n) {
        float2 v = reinterpret_cast<const float2*>(src)[i];
        reinterpret_cast<__half2*>(dst)[i] =
            __halves2half2(__float2half_rn(v.x), __float2half_rn(v.y));
    }
}

__global__ void transpose_h(const float* __restrict__ src,
                            __half* __restrict__ dst, int R, int C)
{
    __shared__ float t[32][33];
    int bx = blockIdx.x * 32, by = blockIdx.y * 32;
    int x = bx + threadIdx.x;
#pragma unroll
    for (int i = 0; i < 32; i += 8)
        t[threadIdx.y + i][threadIdx.x] =
            src[(size_t)(by + threadIdx.y + i) * C + x];
    __syncthreads();
    int xo = by + threadIdx.x;
#pragma unroll
    for (int i = 0; i < 32; i += 8)
        dst[(size_t)(bx + threadIdx.y + i) * R + xo] =
            __float2half_rn(t[threadIdx.x][threadIdx.y + i]);
}

// ---------------------------------------------------------------------------
// output copy + deterministic two-stage sum-of-squares
// ---------------------------------------------------------------------------
__global__ void copy_k(const float* __restrict__ s, float* __restrict__ d,
                       int n4)
{
    int i = blockIdx.x * blockDim.x + threadIdx.x;
    if (i < n4)
        reinterpret_cast<float4*>(d)[i] =
            reinterpret_cast<const float4*>(s)[i];
}

__global__ void sumsq_partial(const float* __restrict__ x, long long n,
                              float* __restrict__ part)
{
    float s = 0.f;
    long long stride = (long long)gridDim.x * blockDim.x;
    for (long long i = (long long)blockIdx.x * blockDim.x + threadIdx.x;
         i < n; i += stride) {
        float v = x[i];
        s = fmaf(v, v, s);
    }
    __shared__ float sh[256];
    sh[threadIdx.x] = s;
    __syncthreads();
    for (int o = 128; o > 0; o >>= 1) {
        if (threadIdx.x < o) sh[threadIdx.x] += sh[threadIdx.x + o];
        __syncthreads();
    }
    if (threadIdx.x == 0) part[blockIdx.x] = sh[0];
}

__global__ void finalize_k(const float* __restrict__ part, int n,
                           float* __restrict__ out)
{
    float s = 0.f;
    for (int i = threadIdx.x; i < n; i += 256) s += part[i];
    __shared__ float sh[256];
    sh[threadIdx.x] = s;
    __syncthreads();
    for (int o = 128; o > 0; o >>= 1) {
        if (threadIdx.x < o) sh[threadIdx.x] += sh[threadIdx.x + o];
        __syncthreads();
    }
    if (threadIdx.x == 0) out[0] = 0.5f * sh[0];
}

// ---------------------------------------------------------------------------
// Launch
// ---------------------------------------------------------------------------
static inline dim3 ggrid(int N) { return dim3(N / 128, MB / 128); }

extern "C" void kernel_launch(void* const* d_in, const int* in_sizes, int n_in,
                              void* d_out, int out_size)
{
    const float* x  = (const float*)d_in[0];
    const float* W0 = (const float*)d_in[1];
    const float* b0 = (const float*)d_in[2];
    const float* W1 = (const float*)d_in[3];
    const float* b1 = (const float*)d_in[4];
    const float* W2 = (const float*)d_in[5];
    const float* b2 = (const float*)d_in[6];
    float* out = (float*)d_out;

    float *r1, *r2, *r3, *e0, *e1, *e2, *part;
    __half *xr, *r1r, *r2r, *r3r, *e0r, *e1r, *e2r;
    __half *w0r, *w1r, *w2r, *wt0, *wt1, *wt2;
    cudaGetSymbolAddress((void**)&r1,  g_r1);
    cudaGetSymbolAddress((void**)&r2,  g_r2);
    cudaGetSymbolAddress((void**)&r3,  g_r3);
    cudaGetSymbolAddress((void**)&e0,  g_e0);
    cudaGetSymbolAddress((void**)&e1,  g_e1);
    cudaGetSymbolAddress((void**)&e2,  g_e2);
    cudaGetSymbolAddress((void**)&xr,  g_xr);
    cudaGetSymbolAddress((void**)&r1r, g_r1r);
    cudaGetSymbolAddress((void**)&r2r, g_r2r);
    cudaGetSymbolAddress((void**)&r3r, g_r3r);
    cudaGetSymbolAddress((void**)&e0r, g_e0r);
    cudaGetSymbolAddress((void**)&e1r, g_e1r);
    cudaGetSymbolAddress((void**)&e2r, g_e2r);
    cudaGetSymbolAddress((void**)&w0r, g_W0r);
    cudaGetSymbolAddress((void**)&w1r, g_W1r);
    cudaGetSymbolAddress((void**)&w2r, g_W2r);
    cudaGetSymbolAddress((void**)&wt0, g_Wt0);
    cudaGetSymbolAddress((void**)&wt1, g_Wt1);
    cudaGetSymbolAddress((void**)&wt2, g_Wt2);
    cudaGetSymbolAddress((void**)&part, g_part);

    cudaFuncSetAttribute(tc_gemm<0>,  cudaFuncAttributeMaxDynamicSharedMemorySize, SMEM_SZ);
    cudaFuncSetAttribute(tc_gemm3<1>, cudaFuncAttributeMaxDynamicSharedMemorySize, SMEM_SZ);
    cudaFuncSetAttribute(tc_gemm3<2>, cudaFuncAttributeMaxDynamicSharedMemorySize, SMEM_SZ);

    // ---- prep: fp16 operand copies (row-major)
    round_h<<<(int)(((long long)MB * D0 / 2 + 255) / 256), 256>>>(x, xr, (long long)MB * D0);
    round_h<<<(int)(((long long)D1 * D0 / 2 + 255) / 256), 256>>>(W0, w0r, (long long)D1 * D0);
    round_h<<<(int)(((long long)D2 * D1 / 2 + 255) / 256), 256>>>(W1, w1r, (long long)D2 * D1);
    round_h<<<(int)(((long long)D3 * D2 / 2 + 255) / 256), 256>>>(W2, w2r, (long long)D3 * D2);
    transpose_h<<<dim3(D0 / 32, D1 / 32), dim3(32, 8)>>>(W0, wt0, D1, D0);
    transpose_h<<<dim3(D1 / 32, D2 / 32), dim3(32, 8)>>>(W1, wt1, D2, D1);
    transpose_h<<<dim3(D2 / 32, D3 / 32), dim3(32, 8)>>>(W2, wt2, D3, D2);

    // ---- feedforward init: r_{i+1} = tanh(r_i @ W_i^T + b_i)
    tc_gemm<0><<<ggrid(D1), 256, SMEM_SZ>>>(xr,  w0r, b0, r1, r1r, D1, D0);
    tc_gemm<0><<<ggrid(D2), 256, SMEM_SZ>>>(r1r, w1r, b1, r2, r2r, D2, D1);
    tc_gemm<0><<<ggrid(D3), 256, SMEM_SZ>>>(r2r, w2r, b2, r3, r3r, D3, D2);

    // ---- fused phase descriptors (largest K first)
    Sub se1 = { r2r, wt1, r1, e1, e1r, D1, D2 };   // 16 tiles, K=2048
    Sub se0 = { r1r, wt0, x,  e0, e0r, D0, D1 };   // 8 tiles,  K=2048
    Sub se2 = { r3r, wt2, r2, e2, e2r, D2, D3 };   // 16 tiles, K=512
    Sub su2 = { e1r, w1r, e2, r2, r2r, D2, D1 };   // 16 tiles, K=2048
    Sub su3 = { e2r, w2r, r3, r3, r3r, D3, D2 };   // 4 tiles,  K=2048
    Sub su1 = { e0r, w0r, e1, r1, r1r, D1, D0 };   // 16 tiles, K=1024

    const dim3 gerr(16 + 8 + 16, MB / 128);
    const dim3 gupd(16 + 4 + 16, MB / 128);

    // ---- 20 PC inference steps: 2 launches per step
    for (int s = 0; s < NSTEPS; s++) {
        tc_gemm3<1><<<gerr, 256, SMEM_SZ>>>(se1, se0, se2, 16, 24);
        tc_gemm3<2><<<gupd, 256, SMEM_SZ>>>(su2, su3, su1, 16, 20);
    }

    // ---- final errors (fused)
    tc_gemm3<1><<<gerr, 256, SMEM_SZ>>>(se1, se0, se2, 16, 24);

    // ---- output r3
    const int n_r3 = MB * D3;
    copy_k<<<(n_r3 / 4 + 255) / 256, 256>>>(r3, out, n_r3 / 4);

    // ---- total_error = 0.5 * (|e0|^2 + |e1|^2 + |e2|^2 + |r3|^2)
    sumsq_partial<<<1024, 256>>>(e0, (long long)MB * D0, part + 0);
    sumsq_partial<<<1024, 256>>>(e1, (long long)MB * D1, part + 1024);
    sumsq_partial<<<1024, 256>>>(e2, (long long)MB * D2, part + 2048);
    sumsq_partial<<<1024, 256>>>(r3, (long long)MB * D3, part + 3072);
    finalize_k<<<1, 256>>>(part, 4096, out + (out_size - 1));
}

// round 14
// speedup vs baseline: 1.0028x; 1.0028x over previous
#include <cuda_runtime.h>
#include <cuda_fp16.h>
#include <cstdint>
#include <math.h>

// ---------------------------------------------------------------------------
// PcLinearBlock: ARCH=(1024,2048,2048,512), BATCH=4096, STEPS=20, LR=0.1
// fp16 mma.sync m16n8k16 + ldmatrix.x4 fragment loads, fp32 accumulate.
// 128x128x64 tile, cp.async 3-stage single-sync pipeline, full XOR swizzle
// (16B chunk ^= row&7) -> conflict-free ldmatrix. Plain row-major fp16
// operand shadows; exact fp32 state carries epilogues/reductions/output.
// Error/update phases fused into single launches via blockIdx routing.
// ---------------------------------------------------------------------------

#define MB 4096
#define D0 1024
#define D1 2048
#define D2 2048
#define D3 512
#define NSTEPS 20
#define LRC 0.1f

// ---- exact fp32 state ----
__device__ __align__(128) float g_r1[(size_t)MB * D1];
__device__ __align__(128) float g_r2[(size_t)MB * D2];
__device__ __align__(128) float g_r3[(size_t)MB * D3];
__device__ __align__(128) float g_e0[(size_t)MB * D0];
__device__ __align__(128) float g_e1[(size_t)MB * D1];
__device__ __align__(128) float g_e2[(size_t)MB * D2];
// ---- fp16-rounded row-major GEMM operand shadows ----
__device__ __align__(128) __half g_xr [(size_t)MB * D0];
__device__ __align__(128) __half g_r1r[(size_t)MB * D1];
__device__ __align__(128) __half g_r2r[(size_t)MB * D2];
__device__ __align__(128) __half g_r3r[(size_t)MB * D3];
__device__ __align__(128) __half g_e0r[(size_t)MB * D0];
__device__ __align__(128) __half g_e1r[(size_t)MB * D1];
__device__ __align__(128) __half g_e2r[(size_t)MB * D2];
__device__ __align__(128) __half g_W0r[(size_t)D1 * D0];
__device__ __align__(128) __half g_W1r[(size_t)D2 * D1];
__device__ __align__(128) __half g_W2r[(size_t)D3 * D2];
__device__ __align__(128) __half g_Wt0[(size_t)D0 * D1];
__device__ __align__(128) __half g_Wt1[(size_t)D1 * D2];
__device__ __align__(128) __half g_Wt2[(size_t)D2 * D3];
__device__ float g_part[4096];

// ---------------------------------------------------------------------------
// helpers
// ---------------------------------------------------------------------------
__device__ __forceinline__ uint32_t s2u(const void* p) {
    uint32_t a;
    asm("{ .reg .u64 t; cvta.to.shared.u64 t, %1; cvt.u32.u64 %0, t; }"
        : "=r"(a) : "l"(p));
    return a;
}
__device__ __forceinline__ void cp16(uint32_t dst, const void* src) {
    asm volatile("cp.async.cg.shared.global [%0], [%1], 16;"
                 :: "r"(dst), "l"(src));
}
__device__ __forceinline__ void ldm4(uint32_t* r, uint32_t addr) {
    asm volatile(
        "ldmatrix.sync.aligned.m8n8.x4.shared.b16 {%0,%1,%2,%3}, [%4];"
        : "=r"(r[0]), "=r"(r[1]), "=r"(r[2]), "=r"(r[3]) : "r"(addr));
}
__device__ __forceinline__ void mma16(float* c, const uint32_t* a,
                                      uint32_t b0, uint32_t b1) {
    asm volatile(
        "mma.sync.aligned.m16n8k16.row.col.f32.f16.f16.f32 "
        "{%0,%1,%2,%3}, {%4,%5,%6,%7}, {%8,%9}, {%0,%1,%2,%3};"
        : "+f"(c[0]), "+f"(c[1]), "+f"(c[2]), "+f"(c[3])
        : "r"(a[0]), "r"(a[1]), "r"(a[2]), "r"(a[3]), "r"(b0), "r"(b1));
}
__device__ __forceinline__ float fast_tanh(float x) {
    float e = __expf(2.0f * x);
    return 1.0f - 2.0f / (e + 1.0f);
}

// ---------------------------------------------------------------------------
// GEMM body:  C[m,n] = sum_k A[m,k]*B[n,k]   (fp16 row-major operands)
// 128x128x64 tile, 256 thr, 3-stage cp.async, ONE __syncthreads per chunk.
// ldmatrix.x4 fragment loads; swizzle: 16B chunk ^= (row & 7).
// EPI 0: D = tanh(acc + X[n]);  EPI 1: D = X - tanh(acc);
// EPI 2: D += LR*(acc - X).   Writes exact fp32 D and fp16 shadow Dr.
// ---------------------------------------------------------------------------
#define STG_B   32768            // A 16KB + B 16KB (128 rows x 128B each)
#define SMEM_SZ (3 * STG_B)

template <int EPI>
__device__ __forceinline__ void gemm_body(
    const __half* __restrict__ A, const __half* __restrict__ B,
    const float* __restrict__ X, float* __restrict__ D,
    __half* __restrict__ Dr, int N, int K, int bm, int bn, char* smem)
{
    const uint32_t sb = s2u(smem);
    const int tid = threadIdx.x;
    const int wid = tid >> 5, lane = tid & 31;
    const int gid = lane >> 2, tig = lane & 3;
    const int warp_m = wid & 1;
    const int warp_n = wid >> 1;

    // global->smem: thread t copies 64B of row t/2 (16B chunks, swizzled)
    const int ar = tid >> 1;
    const int half = tid & 1;
    const __half* gA = A + (size_t)(bm + ar) * K + half * 32;
    const __half* gB = B + (size_t)(bn + ar) * K + half * 32;
    uint32_t sw[4];
#pragma unroll
    for (int i = 0; i < 4; i++) {
        int cc = half * 4 + i;
        sw[i] = (uint32_t)(ar * 128 + ((cc ^ (ar & 7)) * 16));
    }

    const int KT = K >> 6;            // 64 fp16 per chunk = 128B row

    // ---- prologue: stages 0,1
#pragma unroll
    for (int kt = 0; kt < 2; kt++) {
        uint32_t base = sb + kt * STG_B;
        const __half* pa = gA + kt * 64;
        const __half* pb = gB + kt * 64;
#pragma unroll
        for (int i = 0; i < 4; i++) cp16(base + sw[i], pa + i * 8);
#pragma unroll
        for (int i = 0; i < 4; i++) cp16(base + 16384 + sw[i], pb + i * 8);
        asm volatile("cp.async.commit_group;" ::: "memory");
    }

    float acc[4][4][4];
#pragma unroll
    for (int mi = 0; mi < 4; mi++)
#pragma unroll
        for (int ni = 0; ni < 4; ni++)
#pragma unroll
            for (int r = 0; r < 4; r++) acc[mi][ni][r] = 0.f;

    // ldmatrix per-lane addressing:
    //   lanes 0-7:  rows 0-7,  k-lo | lanes 8-15: rows 8-15, k-lo
    //   lanes 16-23: rows 0-7, k-hi | lanes 24-31: rows 8-15, k-hi
    const int mrow = lane & 15;       // row within 16-row fragment
    const int khi  = lane >> 4;       // 0 = k0-7 chunk, 1 = k8-15 chunk
    const int rx   = mrow & 7;        // swizzle key (row & 7)
    const uint32_t arow0 = (uint32_t)((warp_m * 64 + mrow) * 128);
    const uint32_t brow0 = (uint32_t)((warp_n * 32 + mrow) * 128);

    // ---- mainloop: one barrier per 64-k chunk
    for (int kt = 0; kt < KT; kt++) {
        asm volatile("cp.async.wait_group 1;" ::: "memory");
        __syncthreads();
        const int kn = kt + 2;
        if (kn < KT) {
            uint32_t base = sb + (kn % 3) * STG_B;
            const __half* pa = gA + kn * 64;
            const __half* pb = gB + kn * 64;
#pragma unroll
            for (int i = 0; i < 4; i++) cp16(base + sw[i], pa + i * 8);
#pragma unroll
            for (int i = 0; i < 4; i++) cp16(base + 16384 + sw[i], pb + i * 8);
        }
        asm volatile("cp.async.commit_group;" ::: "memory");

        const uint32_t sA = sb + (kt % 3) * STG_B;
        const uint32_t sB = sA + 16384;

#pragma unroll
        for (int ks = 0; ks < 4; ks++) {            // 4 x k16 per chunk
            const uint32_t cb = (uint32_t)(((ks * 2 + khi) ^ rx) * 16);
            uint32_t a[4][4], b[2][4];
#pragma unroll
            for (int mi = 0; mi < 4; mi++)
                ldm4(a[mi], sA + arow0 + (uint32_t)(mi * 16 * 128) + cb);
#pragma unroll
            for (int nj = 0; nj < 2; nj++)
                ldm4(b[nj], sB + brow0 + (uint32_t)(nj * 16 * 128) + cb);
#pragma unroll
            for (int mi = 0; mi < 4; mi++)
#pragma unroll
                for (int ni = 0; ni < 4; ni++)
                    mma16(acc[mi][ni], a[mi],
                          b[ni >> 1][ni & 1], b[ni >> 1][(ni & 1) + 2]);
        }
    }

    // ---- fused epilogue: exact fp32 store + fp16 shadow
#pragma unroll
    for (int mi = 0; mi < 4; mi++) {
        const int gm = bm + warp_m * 64 + mi * 16 + gid;
#pragma unroll
        for (int ni = 0; ni < 4; ni++) {
            const int gn = bn + warp_n * 32 + ni * 8 + 2 * tig;   // even
            const size_t i0 = (size_t)gm * N + gn;
            const size_t i1 = i0 + (size_t)8 * N;
            const float* c = acc[mi][ni];
            float2 o0, o1;
            if (EPI == 0) {
                float b0v = X[gn], b1v = X[gn + 1];
                o0.x = fast_tanh(c[0] + b0v);
                o0.y = fast_tanh(c[1] + b1v);
                o1.x = fast_tanh(c[2] + b0v);
                o1.y = fast_tanh(c[3] + b1v);
            } else if (EPI == 1) {
                float2 x0 = *reinterpret_cast<const float2*>(&X[i0]);
                float2 x1 = *reinterpret_cast<const float2*>(&X[i1]);
                o0.x = x0.x - fast_tanh(c[0]);
                o0.y = x0.y - fast_tanh(c[1]);
                o1.x = x1.x - fast_tanh(c[2]);
                o1.y = x1.y - fast_tanh(c[3]);
            } else {
                float2 x0 = *reinterpret_cast<const float2*>(&X[i0]);
                float2 x1 = *reinterpret_cast<const float2*>(&X[i1]);
                float2 d0 = *reinterpret_cast<const float2*>(&D[i0]);
                float2 d1 = *reinterpret_cast<const float2*>(&D[i1]);
                o0.x = d0.x + LRC * (c[0] - x0.x);
                o0.y = d0.y + LRC * (c[1] - x0.y);
                o1.x = d1.x + LRC * (c[2] - x1.x);
                o1.y = d1.y + LRC * (c[3] - x1.y);
            }
            *reinterpret_cast<float2*>(&D[i0]) = o0;
            *reinterpret_cast<float2*>(&D[i1]) = o1;
            *reinterpret_cast<__half2*>(&Dr[i0]) =
                __halves2half2(__float2half_rn(o0.x), __float2half_rn(o0.y));
            *reinterpret_cast<__half2*>(&Dr[i1]) =
                __halves2half2(__float2half_rn(o1.x), __float2half_rn(o1.y));
        }
    }
}

// ---- single-GEMM kernel (feedforward) ----
template <int EPI>
__global__ void __launch_bounds__(256, 2)
tc_gemm(const __half* __restrict__ A, const __half* __restrict__ B,
        const float* __restrict__ X, float* __restrict__ D,
        __half* __restrict__ Dr, int N, int K)
{
    extern __shared__ char smem[];
    gemm_body<EPI>(A, B, X, D, Dr, N, K,
                   blockIdx.y * 128, blockIdx.x * 128, smem);
}

// ---- fused 3-GEMM kernel (error / update phases) ----
struct Sub {
    const __half* A; const __half* B; const float* X;
    float* D; __half* Dr; int N; int K;
};

template <int EPI>
__global__ void __launch_bounds__(256, 2)
tc_gemm3(Sub s0, Sub s1, Sub s2, int t0, int t1)
{
    extern __shared__ char smem[];
    const int bx = blockIdx.x;
    const __half *A, *B; const float* X; float* D; __half* Dr; int N, K, bn;
    if (bx < t0)      { A=s0.A; B=s0.B; X=s0.X; D=s0.D; Dr=s0.Dr;
                        N=s0.N; K=s0.K; bn = bx * 128; }
    else if (bx < t1) { A=s1.A; B=s1.B; X=s1.X; D=s1.D; Dr=s1.Dr;
                        N=s1.N; K=s1.K; bn = (bx - t0) * 128; }
    else              { A=s2.A; B=s2.B; X=s2.X; D=s2.D; Dr=s2.Dr;
                        N=s2.N; K=s2.K; bn = (bx - t1) * 128; }
    gemm_body<EPI>(A, B, X, D, Dr, N, K, blockIdx.y * 128, bn, smem);
}

// ---------------------------------------------------------------------------
// prep kernels: fp32 -> fp16 (and transpose for Wt); plain row-major
// ---------------------------------------------------------------------------
__global__ void round_h(const float* __restrict__ src,
                        __half* __restrict__ dst, long long n)
{
    long long i = (long long)blockIdx.x * blockDim.x + threadIdx.x;
    if (i * 2 < n) {
        float2 v = reinterpret_cast<const float2*>(src)[i];
        reinterpret_cast<__half2*>(dst)[i] =
            __halves2half2(__float2half_rn(v.x), __float2half_rn(v.y));
    }
}

__global__ void transpose_h(const float* __restrict__ src,
                            __half* __restrict__ dst, int R, int C)
{
    __shared__ float t[32][33];
    int bx = blockIdx.x * 32, by = blockIdx.y * 32;
    int x = bx + threadIdx.x;
#pragma unroll
    for (int i = 0; i < 32; i += 8)
        t[threadIdx.y + i][threadIdx.x] =
            src[(size_t)(by + threadIdx.y + i) * C + x];
    __syncthreads();
    int xo = by + threadIdx.x;
#pragma unroll
    for (int i = 0; i < 32; i += 8)
        dst[(size_t)(bx + threadIdx.y + i) * R + xo] =
            __float2half_rn(t[threadIdx.x][threadIdx.y + i]);
}

// ---------------------------------------------------------------------------
// output copy + deterministic two-stage sum-of-squares
// ---------------------------------------------------------------------------
__global__ void copy_k(const float* __restrict__ s, float* __restrict__ d,
                       int n4)
{
    int i = blockIdx.x * blockDim.x + threadIdx.x;
    if (i < n4)
        reinterpret_cast<float4*>(d)[i] =
            reinterpret_cast<const float4*>(s)[i];
}

__global__ void sumsq_partial(const float* __restrict__ x, long long n,
                              float* __restrict__ part)
{
    float s = 0.f;
    long long stride = (long long)gridDim.x * blockDim.x;
    for (long long i = (long long)blockIdx.x * blockDim.x + threadIdx.x;
         i < n; i += stride) {
        float v = x[i];
        s = fmaf(v, v, s);
    }
    __shared__ float sh[256];
    sh[threadIdx.x] = s;
    __syncthreads();
    for (int o = 128; o > 0; o >>= 1) {
        if (threadIdx.x < o) sh[threadIdx.x] += sh[threadIdx.x + o];
        __syncthreads();
    }
    if (threadIdx.x == 0) part[blockIdx.x] = sh[0];
}

__global__ void finalize_k(const float* __restrict__ part, int n,
                           float* __restrict__ out)
{
    float s = 0.f;
    for (int i = threadIdx.x; i < n; i += 256) s += part[i];
    __shared__ float sh[256];
    sh[threadIdx.x] = s;
    __syncthreads();
    for (int o = 128; o > 0; o >>= 1) {
        if (threadIdx.x < o) sh[threadIdx.x] += sh[threadIdx.x + o];
        __syncthreads();
    }
    if (threadIdx.x == 0) out[0] = 0.5f * sh[0];
}

// ---------------------------------------------------------------------------
// Launch
// ---------------------------------------------------------------------------
static inline dim3 ggrid(int N) { return dim3(N / 128, MB / 128); }

extern "C" void kernel_launch(void* const* d_in, const int* in_sizes, int n_in,
                              void* d_out, int out_size)
{
    const float* x  = (const float*)d_in[0];
    const float* W0 = (const float*)d_in[1];
    const float* b0 = (const float*)d_in[2];
    const float* W1 = (const float*)d_in[3];
    const float* b1 = (const float*)d_in[4];
    const float* W2 = (const float*)d_in[5];
    const float* b2 = (const float*)d_in[6];
    float* out = (float*)d_out;

    float *r1, *r2, *r3, *e0, *e1, *e2, *part;
    __half *xr, *r1r, *r2r, *r3r, *e0r, *e1r, *e2r;
    __half *w0r, *w1r, *w2r, *wt0, *wt1, *wt2;
    cudaGetSymbolAddress((void**)&r1,  g_r1);
    cudaGetSymbolAddress((void**)&r2,  g_r2);
    cudaGetSymbolAddress((void**)&r3,  g_r3);
    cudaGetSymbolAddress((void**)&e0,  g_e0);
    cudaGetSymbolAddress((void**)&e1,  g_e1);
    cudaGetSymbolAddress((void**)&e2,  g_e2);
    cudaGetSymbolAddress((void**)&xr,  g_xr);
    cudaGetSymbolAddress((void**)&r1r, g_r1r);
    cudaGetSymbolAddress((void**)&r2r, g_r2r);
    cudaGetSymbolAddress((void**)&r3r, g_r3r);
    cudaGetSymbolAddress((void**)&e0r, g_e0r);
    cudaGetSymbolAddress((void**)&e1r, g_e1r);
    cudaGetSymbolAddress((void**)&e2r, g_e2r);
    cudaGetSymbolAddress((void**)&w0r, g_W0r);
    cudaGetSymbolAddress((void**)&w1r, g_W1r);
    cudaGetSymbolAddress((void**)&w2r, g_W2r);
    cudaGetSymbolAddress((void**)&wt0, g_Wt0);
    cudaGetSymbolAddress((void**)&wt1, g_Wt1);
    cudaGetSymbolAddress((void**)&wt2, g_Wt2);
    cudaGetSymbolAddress((void**)&part, g_part);

    cudaFuncSetAttribute(tc_gemm<0>,  cudaFuncAttributeMaxDynamicSharedMemorySize, SMEM_SZ);
    cudaFuncSetAttribute(tc_gemm3<1>, cudaFuncAttributeMaxDynamicSharedMemorySize, SMEM_SZ);
    cudaFuncSetAttribute(tc_gemm3<2>, cudaFuncAttributeMaxDynamicSharedMemorySize, SMEM_SZ);

    // ---- prep: fp16 operand copies (row-major)
    round_h<<<(int)(((long long)MB * D0 / 2 + 255) / 256), 256>>>(x, xr, (long long)MB * D0);
    round_h<<<(int)(((long long)D1 * D0 / 2 + 255) / 256), 256>>>(W0, w0r, (long long)D1 * D0);
    round_h<<<(int)(((long long)D2 * D1 / 2 + 255) / 256), 256>>>(W1, w1r, (long long)D2 * D1);
    round_h<<<(int)(((long long)D3 * D2 / 2 + 255) / 256), 256>>>(W2, w2r, (long long)D3 * D2);
    transpose_h<<<dim3(D0 / 32, D1 / 32), dim3(32, 8)>>>(W0, wt0, D1, D0);
    transpose_h<<<dim3(D1 / 32, D2 / 32), dim3(32, 8)>>>(W1, wt1, D2, D1);
    transpose_h<<<dim3(D2 / 32, D3 / 32), dim3(32, 8)>>>(W2, wt2, D3, D2);

    // ---- feedforward init: r_{i+1} = tanh(r_i @ W_i^T + b_i)
    tc_gemm<0><<<ggrid(D1), 256, SMEM_SZ>>>(xr,  w0r, b0, r1, r1r, D1, D0);
    tc_gemm<0><<<ggrid(D2), 256, SMEM_SZ>>>(r1r, w1r, b1, r2, r2r, D2, D1);
    tc_gemm<0><<<ggrid(D3), 256, SMEM_SZ>>>(r2r, w2r, b2, r3, r3r, D3, D2);

    // ---- fused phase descriptors (largest K first)
    Sub se1 = { r2r, wt1, r1, e1, e1r, D1, D2 };   // 16 tiles, K=2048
    Sub se0 = { r1r, wt0, x,  e0, e0r, D0, D1 };   // 8 tiles,  K=2048
    Sub se2 = { r3r, wt2, r2, e2, e2r, D2, D3 };   // 16 tiles, K=512
    Sub su2 = { e1r, w1r, e2, r2, r2r, D2, D1 };   // 16 tiles, K=2048
    Sub su3 = { e2r, w2r, r3, r3, r3r, D3, D2 };   // 4 tiles,  K=2048
    Sub su1 = { e0r, w0r, e1, r1, r1r, D1, D0 };   // 16 tiles, K=1024

    const dim3 gerr(16 + 8 + 16, MB / 128);
    const dim3 gupd(16 + 4 + 16, MB / 128);

    // ---- 20 PC inference steps: 2 launches per step
    for (int s = 0; s < NSTEPS; s++) {
        tc_gemm3<1><<<gerr, 256, SMEM_SZ>>>(se1, se0, se2, 16, 24);
        tc_gemm3<2><<<gupd, 256, SMEM_SZ>>>(su2, su3, su1, 16, 20);
    }

    // ---- final errors (fused)
    tc_gemm3<1><<<gerr, 256, SMEM_SZ>>>(se1, se0, se2, 16, 24);

    // ---- output r3
    const int n_r3 = MB * D3;
    copy_k<<<(n_r3 / 4 + 255) / 256, 256>>>(r3, out, n_r3 / 4);

    // ---- total_error = 0.5 * (|e0|^2 + |e1|^2 + |e2|^2 + |r3|^2)
    sumsq_partial<<<1024, 256>>>(e0, (long long)MB * D0, part + 0);
    sumsq_partial<<<1024, 256>>>(e1, (long long)MB * D1, part + 1024);
    sumsq_partial<<<1024, 256>>>(e2, (long long)MB * D2, part + 2048);
    sumsq_partial<<<1024, 256>>>(r3, (long long)MB * D3, part + 3072);
    finalize_k<<<1, 256>>>(part, 4096, out + (out_size - 1));
}